// round 4
// baseline (speedup 1.0000x reference)
#include <cuda_runtime.h>

// YOLOv1 loss, GB300 sm_103a — persistent kernel, cp.async double-buffered
// pipeline, 128 threads/block for 28 warps/SM residency.
//
// pred:   (16384, 7, 7, 30) f32   d_in[0]
// target: (16384, 7, 7, 30) f32   d_in[1]
// out:    scalar f32

#define N_BATCH 16384
#define N_CELLS (N_BATCH * 49)          // 802816
#define TPB 128
#define TILE 128                         // cells per tile (1 per thread)
#define TILE_FLOATS (TILE * 30)          // 3840
#define TILE_VEC4 (TILE_FLOATS / 4)      // 960
#define NTILES (N_CELLS / TILE)          // 6272 (divides exactly)
#define GRID (7 * 148)                   // 1036 persistent blocks (7/SM by smem)

__device__ double g_acc;
__device__ unsigned int g_count;

__device__ __forceinline__ void cp16(void* smem_dst, const void* gmem_src) {
    unsigned int s = (unsigned int)__cvta_generic_to_shared(smem_dst);
    asm volatile("cp.async.cg.shared.global [%0], [%1], 16;\n"
                 :: "r"(s), "l"(gmem_src) : "memory");
}
__device__ __forceinline__ void cp_commit() {
    asm volatile("cp.async.commit_group;\n" ::: "memory");
}
__device__ __forceinline__ void cp_wait1() {
    asm volatile("cp.async.wait_group 1;\n" ::: "memory");
}
__device__ __forceinline__ void cp_wait0() {
    asm volatile("cp.async.wait_group 0;\n" ::: "memory");
}

__global__ void __launch_bounds__(TPB, 7) yolo_loss_kernel(
    const float* __restrict__ pred,
    const float* __restrict__ targ,
    float* __restrict__ out)
{
    __shared__ __align__(16) float sp[2][TILE_FLOATS];
    __shared__ __align__(16) float st[2][TILE_FLOATS];
    __shared__ float warpsum[TPB / 32];
    __shared__ unsigned int s_ticket;

    const int tid = threadIdx.x;

    // ---- prefetch: tile -> stage buffer (fully coalesced float4 LDGSTS) ----
    auto prefetch = [&](int buf, int tile) {
        const float4* gp = (const float4*)(pred + (size_t)tile * TILE_FLOATS);
        const float4* gt = (const float4*)(targ + (size_t)tile * TILE_FLOATS);
        float4* s4p = (float4*)sp[buf];
        float4* s4t = (float4*)st[buf];
#pragma unroll
        for (int i = 0; i < 7; i++) {           // 7*128 = 896 of 960
            cp16(s4p + tid + i * TPB, gp + tid + i * TPB);
            cp16(s4t + tid + i * TPB, gt + tid + i * TPB);
        }
        if (tid < TILE_VEC4 - 7 * TPB) {        // remaining 64
            cp16(s4p + tid + 7 * TPB, gp + tid + 7 * TPB);
            cp16(s4t + tid + 7 * TPB, gt + tid + 7 * TPB);
        }
    };

    float acc = 0.0f;
    int cur = 0;
    int tile = blockIdx.x;

    prefetch(cur, tile);
    cp_commit();

    for (; tile < NTILES; tile += GRID) {
        const int next = tile + GRID;
        if (next < NTILES) {
            prefetch(cur ^ 1, next);
            cp_commit();
            cp_wait1();                          // current tile's group done
        } else {
            cp_wait0();
        }
        __syncthreads();                         // cross-thread smem visibility

        // ---- per-cell loss (thread tid owns cell tid of this tile) ----
        const float* p = sp[cur] + tid * 30;
        const float* t = st[cur] + tid * 30;

        const float coo = (t[4] > 0.0f) ? 1.0f : 0.0f;
        const float noo = 1.0f - coo;

        float d4 = p[4] - t[4];
        float d9 = p[9] - t[9];
        float loss = 0.5f * noo * (d4 * d4 + d9 * d9);

        float cls = 0.0f;
#pragma unroll
        for (int k = 10; k < 30; k++) {
            float d = p[k] - t[k];
            cls += d * d;
        }
        loss += coo * cls;

        // degenerate IoU, matching the reference exactly:
        // inter = 1 iff (rb-lt)<0 in BOTH dims, else 0
        const float t_ltx = t[0] - 0.5f * t[2];
        const float t_lty = t[1] - 0.5f * t[3];
        const float t_rbx = t[0] + 0.5f * t[2];
        const float t_rby = t[1] + 0.5f * t[3];
        const float area2 = (t_rbx - t_ltx) * (t_rby - t_lty);

        float iou[2];
#pragma unroll
        for (int b = 0; b < 2; b++) {
            const float* pb = p + b * 5;
            float p_ltx = pb[0] - 0.5f * pb[2];
            float p_lty = pb[1] - 0.5f * pb[3];
            float p_rbx = pb[0] + 0.5f * pb[2];
            float p_rby = pb[1] + 0.5f * pb[3];
            float ltx = fmaxf(p_ltx, t_ltx);
            float lty = fmaxf(p_lty, t_lty);
            float rbx = fminf(p_rbx, t_rbx);
            float rby = fminf(p_rby, t_rby);
            float wh0 = (rbx - ltx < 0.0f) ? 1.0f : 0.0f;
            float wh1 = (rby - lty < 0.0f) ? 1.0f : 0.0f;
            float inter = wh0 * wh1;
            float area1 = (p_rbx - p_ltx) * (p_rby - p_lty);
            iou[b] = inter / (area1 + area2 - inter);
        }
        const int idx = (iou[1] > iou[0]) ? 1 : 0;   // first index on ties
        const float* rp = p + idx * 5;
        const float* rt = t + idx * 5;

        float dc = rp[4] - rt[4];
        loss += coo * dc * dc;

        float dx = rp[0] - rt[0];
        float dy = rp[1] - rt[1];
        float wp2 = (coo > 0.0f) ? rp[2] : 1.0f;
        float wp3 = (coo > 0.0f) ? rp[3] : 1.0f;
        float wt2 = (coo > 0.0f) ? rt[2] : 1.0f;
        float wt3 = (coo > 0.0f) ? rt[3] : 1.0f;
        float dw = sqrtf(wp2) - sqrtf(wt2);
        float dh = sqrtf(wp3) - sqrtf(wt3);
        loss += 5.0f * coo * (dx * dx + dy * dy + dw * dw + dh * dh);

        acc += loss;

        __syncthreads();   // all threads done reading buf[cur] before reuse
        cur ^= 1;
    }

    // ---- block reduction ----
#pragma unroll
    for (int o = 16; o > 0; o >>= 1)
        acc += __shfl_xor_sync(0xFFFFFFFFu, acc, o);
    if ((tid & 31) == 0)
        warpsum[tid >> 5] = acc;
    __syncthreads();

    if (tid == 0) {
        float s = 0.0f;
#pragma unroll
        for (int w = 0; w < TPB / 32; w++)
            s += warpsum[w];
        atomicAdd(&g_acc, (double)s * (1.0 / (double)N_BATCH));
        __threadfence();
        s_ticket = atomicAdd(&g_count, 1u);
    }
    __syncthreads();

    // ---- last block publishes scalar and resets state ----
    if (tid == 0 && s_ticket == GRID - 1) {
        double total = atomicAdd(&g_acc, 0.0);
        out[0] = (float)total;
        g_acc = 0.0;
        g_count = 0u;
    }
}

extern "C" void kernel_launch(void* const* d_in, const int* in_sizes, int n_in,
                              void* d_out, int out_size) {
    (void)in_sizes; (void)n_in; (void)out_size;
    const float* pred = (const float*)d_in[0];
    const float* targ = (const float*)d_in[1];
    float* out = (float*)d_out;

    yolo_loss_kernel<<<GRID, TPB>>>(pred, targ, out);
}

// round 9
// speedup vs baseline: 1.1166x; 1.1166x over previous
#include <cuda_runtime.h>

// YOLOv1 loss, GB300 sm_103a — persistent 64-thread blocks (proven R3 shape),
// cp.async double-buffered pipeline, ONE barrier per tile, balanced CONTIGUOUS
// per-block tile chunks (no wave tail, better DRAM page locality).
//
// pred:   (16384, 7, 7, 30) f32   d_in[0]
// target: (16384, 7, 7, 30) f32   d_in[1]
// out:    scalar f32
//
// smem/block = 2 stages x 2 tensors x 64 cells x 120B = 30720B -> 7 blocks/SM.

#define N_BATCH 16384
#define N_CELLS (N_BATCH * 49)          // 802816
#define TPB 64
#define TILE 64                          // cells per tile (1 per thread)
#define TILE_FLOATS (TILE * 30)          // 1920 floats per tensor per tile
#define VEC4_PER_TENSOR (TILE_FLOATS / 4) // 480
#define NTILES (N_CELLS / TILE)          // 12544 (exact)
#define GRID (7 * 148)                   // 1036 persistent blocks, 7/SM

__device__ double g_acc;
__device__ unsigned int g_count;

__device__ __forceinline__ void cp16(void* smem_dst, const void* gmem_src) {
    unsigned int s = (unsigned int)__cvta_generic_to_shared(smem_dst);
    asm volatile("cp.async.cg.shared.global [%0], [%1], 16;\n"
                 :: "r"(s), "l"(gmem_src) : "memory");
}
__device__ __forceinline__ void cp_commit() {
    asm volatile("cp.async.commit_group;\n" ::: "memory");
}
__device__ __forceinline__ void cp_wait0() {
    asm volatile("cp.async.wait_group 0;\n" ::: "memory");
}

__global__ void __launch_bounds__(TPB, 7) yolo_loss_kernel(
    const float* __restrict__ pred,
    const float* __restrict__ targ,
    float* __restrict__ out)
{
    __shared__ __align__(16) float sp[2][TILE_FLOATS];
    __shared__ __align__(16) float st[2][TILE_FLOATS];
    __shared__ float warpsum[TPB / 32];
    __shared__ unsigned int s_ticket;

    const int tid = threadIdx.x;

    // ---- prefetch: tile -> stage buffer (coalesced float4 LDGSTS) ----
    auto prefetch = [&](int buf, int tile) {
        const float4* gp = (const float4*)(pred + (size_t)tile * TILE_FLOATS);
        const float4* gt = (const float4*)(targ + (size_t)tile * TILE_FLOATS);
        float4* s4p = (float4*)sp[buf];
        float4* s4t = (float4*)st[buf];
#pragma unroll
        for (int i = 0; i < 7; i++) {            // 7*64 = 448 of 480
            cp16(s4p + tid + i * TPB, gp + tid + i * TPB);
            cp16(s4t + tid + i * TPB, gt + tid + i * TPB);
        }
        if (tid < VEC4_PER_TENSOR - 7 * TPB) {   // remaining 32
            cp16(s4p + tid + 7 * TPB, gp + tid + 7 * TPB);
            cp16(s4t + tid + 7 * TPB, gt + tid + 7 * TPB);
        }
    };

    // ---- balanced contiguous chunk for this block ----
    const int b = blockIdx.x;
    const int base = NTILES / GRID;              // 12
    const int rem = NTILES % GRID;               // 112
    const int cnt = base + (b < rem ? 1 : 0);    // 12 or 13 tiles
    int tile = b * base + (b < rem ? b : rem);   // contiguous start

    float acc = 0.0f;
    int cur = 0;

    prefetch(0, tile);
    cp_commit();

    for (int k = 0; k < cnt; k++) {
        cp_wait0();           // this block's pending group (tile k) complete
        __syncthreads();      // async-proxy visibility + all lanes done with
                              // the buffer about to be refilled
        if (k + 1 < cnt) {
            prefetch(cur ^ 1, tile + 1);         // overlap with compute below
            cp_commit();
        }

        // ---- per-cell loss (thread tid owns cell tid of this tile) ----
        const float* p = sp[cur] + tid * 30;
        const float* t = st[cur] + tid * 30;

        const float coo = (t[4] > 0.0f) ? 1.0f : 0.0f;
        const float noo = 1.0f - coo;

        float d4 = p[4] - t[4];
        float d9 = p[9] - t[9];
        float loss = 0.5f * noo * (d4 * d4 + d9 * d9);

        float cls = 0.0f;
#pragma unroll
        for (int kk = 10; kk < 30; kk++) {
            float d = p[kk] - t[kk];
            cls += d * d;
        }
        loss += coo * cls;

        // degenerate IoU, matching the reference exactly:
        // inter = 1 iff (rb-lt)<0 in BOTH dims, else 0
        const float t_ltx = t[0] - 0.5f * t[2];
        const float t_lty = t[1] - 0.5f * t[3];
        const float t_rbx = t[0] + 0.5f * t[2];
        const float t_rby = t[1] + 0.5f * t[3];
        const float area2 = (t_rbx - t_ltx) * (t_rby - t_lty);

        float iou[2];
#pragma unroll
        for (int bb = 0; bb < 2; bb++) {
            const float* pb = p + bb * 5;
            float p_ltx = pb[0] - 0.5f * pb[2];
            float p_lty = pb[1] - 0.5f * pb[3];
            float p_rbx = pb[0] + 0.5f * pb[2];
            float p_rby = pb[1] + 0.5f * pb[3];
            float ltx = fmaxf(p_ltx, t_ltx);
            float lty = fmaxf(p_lty, t_lty);
            float rbx = fminf(p_rbx, t_rbx);
            float rby = fminf(p_rby, t_rby);
            float wh0 = (rbx - ltx < 0.0f) ? 1.0f : 0.0f;
            float wh1 = (rby - lty < 0.0f) ? 1.0f : 0.0f;
            float inter = wh0 * wh1;
            float area1 = (p_rbx - p_ltx) * (p_rby - p_lty);
            iou[bb] = inter / (area1 + area2 - inter);
        }
        const int idx = (iou[1] > iou[0]) ? 1 : 0;   // first index on ties
        const float* rp = p + idx * 5;
        const float* rt = t + idx * 5;

        float dc = rp[4] - rt[4];
        loss += coo * dc * dc;

        float dx = rp[0] - rt[0];
        float dy = rp[1] - rt[1];
        float wp2 = (coo > 0.0f) ? rp[2] : 1.0f;
        float wp3 = (coo > 0.0f) ? rp[3] : 1.0f;
        float wt2 = (coo > 0.0f) ? rt[2] : 1.0f;
        float wt3 = (coo > 0.0f) ? rt[3] : 1.0f;
        float dw = sqrtf(wp2) - sqrtf(wt2);
        float dh = sqrtf(wp3) - sqrtf(wt3);
        loss += 5.0f * coo * (dx * dx + dy * dy + dw * dw + dh * dh);

        acc += loss;

        cur ^= 1;
        tile += 1;
        // no end barrier: buffer reuse is protected by the next
        // iteration's top barrier (prefetch is issued only after it)
    }

    // ---- block reduction ----
#pragma unroll
    for (int o = 16; o > 0; o >>= 1)
        acc += __shfl_xor_sync(0xFFFFFFFFu, acc, o);
    if ((tid & 31) == 0)
        warpsum[tid >> 5] = acc;
    __syncthreads();

    if (tid == 0) {
        float s = warpsum[0] + warpsum[1];
        atomicAdd(&g_acc, (double)s * (1.0 / (double)N_BATCH));
        __threadfence();
        s_ticket = atomicAdd(&g_count, 1u);
    }
    __syncthreads();

    // ---- last block publishes scalar and resets state ----
    if (tid == 0 && s_ticket == GRID - 1) {
        double total = atomicAdd(&g_acc, 0.0);
        out[0] = (float)total;
        g_acc = 0.0;
        g_count = 0u;
    }
}

extern "C" void kernel_launch(void* const* d_in, const int* in_sizes, int n_in,
                              void* d_out, int out_size) {
    (void)in_sizes; (void)n_in; (void)out_size;
    const float* pred = (const float*)d_in[0];
    const float* targ = (const float*)d_in[1];
    float* out = (float*)d_out;

    yolo_loss_kernel<<<GRID, TPB>>>(pred, targ, out);
}